// round 6
// baseline (speedup 1.0000x reference)
#include <cuda_runtime.h>
#include <cuda_bf16.h>
#include <cstdint>

#define ROW_LEN 4096
#define THREADS 256
#define V4 4                 // 4096 floats / 4 per float4 / 256 threads
#define SM_COUNT 148
#define CTAS_PER_SM 8

__global__ void __launch_bounds__(THREADS, CTAS_PER_SM)
quant_rowwise_persistent(const float* __restrict__ x, float* __restrict__ out,
                         int n_rows)
{
    __shared__ float smn[8], smx[8];
    const int t   = threadIdx.x;
    const int wid = t >> 5;
    const int lid = t & 31;

#pragma unroll 1
    for (int row = blockIdx.x; row < n_rows; row += gridDim.x) {
        const size_t base = (size_t)row * ROW_LEN;
        const float4* __restrict__ xr   = reinterpret_cast<const float4*>(x + base);
        float4* __restrict__       outr = reinterpret_cast<float4*>(out + base);

        // front-batched vector loads: 4 independent LDG.128.cs per thread
        float4 v[V4];
#pragma unroll
        for (int k = 0; k < V4; ++k)
            v[k] = __ldcs(&xr[t + k * THREADS]);

        // local min/max over 16 values
        float mn = v[0].x, mx = v[0].x;
#pragma unroll
        for (int k = 0; k < V4; ++k) {
            mn = fminf(mn, fminf(fminf(v[k].x, v[k].y), fminf(v[k].z, v[k].w)));
            mx = fmaxf(mx, fmaxf(fmaxf(v[k].x, v[k].y), fmaxf(v[k].z, v[k].w)));
        }

        // warp reduce
#pragma unroll
        for (int off = 16; off > 0; off >>= 1) {
            mn = fminf(mn, __shfl_xor_sync(0xFFFFFFFFu, mn, off));
            mx = fmaxf(mx, __shfl_xor_sync(0xFFFFFFFFu, mx, off));
        }

        // block reduce: leaders publish, ONE barrier, everyone folds redundantly
        if (lid == 0) { smn[wid] = mn; smx[wid] = mx; }
        __syncthreads();

        float bmn = smn[0], bmx = smx[0];
#pragma unroll
        for (int i = 1; i < 8; ++i) {
            bmn = fminf(bmn, smn[i]);
            bmx = fmaxf(bmx, smx[i]);
        }
        float scale = (bmx - bmn) * (1.0f / 255.0f);
        scale = fminf(fmaxf(scale, 1e-5f), 1e4f);
        float zp = -bmn / scale;
        zp = fminf(fmaxf(zp, -1e4f), 1e4f);
        const float inv = 1.0f / scale;

        // fake quant-dequant, streaming vector stores
#pragma unroll
        for (int k = 0; k < V4; ++k) {
            float4 r;
            float q;
            q = rintf(v[k].x * inv) + zp; q = fminf(fmaxf(q, 0.0f), 255.0f); r.x = (q - zp) * scale;
            q = rintf(v[k].y * inv) + zp; q = fminf(fmaxf(q, 0.0f), 255.0f); r.y = (q - zp) * scale;
            q = rintf(v[k].z * inv) + zp; q = fminf(fmaxf(q, 0.0f), 255.0f); r.z = (q - zp) * scale;
            q = rintf(v[k].w * inv) + zp; q = fminf(fmaxf(q, 0.0f), 255.0f); r.w = (q - zp) * scale;
            __stcs(&outr[t + k * THREADS], r);
        }

        // barrier before smn/smx reuse next iteration
        __syncthreads();
    }
}

extern "C" void kernel_launch(void* const* d_in, const int* in_sizes, int n_in,
                              void* d_out, int out_size)
{
    const float* x = (const float*)d_in[0];
    float* out = (float*)d_out;
    const int n_rows = in_sizes[0] / ROW_LEN;   // 16384
    const int grid = SM_COUNT * CTAS_PER_SM;    // 1184 = exactly one wave
    quant_rowwise_persistent<<<grid, THREADS>>>(x, out, n_rows);
}

// round 7
// speedup vs baseline: 1.1088x; 1.1088x over previous
#include <cuda_runtime.h>
#include <cuda_bf16.h>
#include <cstdint>

#define ROW_LEN   4096
#define THREADS   128          // 4 warps per CTA, each warp owns one full row
#define WARPS_CTA 4
#define NV4       32           // float4 per lane: 4096 / 4 / 32 lanes

__global__ void __launch_bounds__(THREADS, 3)
quant_warprow_reg(const float* __restrict__ x, float* __restrict__ out)
{
    const int wid = threadIdx.x >> 5;
    const int lid = threadIdx.x & 31;
    const size_t row  = (size_t)blockIdx.x * WARPS_CTA + wid;
    const size_t base = row * ROW_LEN;

    const float4* __restrict__ xr   = reinterpret_cast<const float4*>(x + base);
    float4* __restrict__       outr = reinterpret_cast<float4*>(out + base);

    // ---- entire row into registers: 32 front-batched LDG.128.cs per lane ----
    float4 v[NV4];
#pragma unroll
    for (int k = 0; k < NV4; ++k)
        v[k] = __ldcs(&xr[lid + k * 32]);

    // ---- min/max reduce over 128 values, 4 independent chains for ILP ----
    float mn0 = v[0].x, mx0 = v[0].x;
    float mn1 = v[1].x, mx1 = v[1].x;
    float mn2 = v[2].x, mx2 = v[2].x;
    float mn3 = v[3].x, mx3 = v[3].x;
#pragma unroll
    for (int k = 0; k < NV4; k += 4) {
        mn0 = fminf(mn0, fminf(fminf(v[k+0].x, v[k+0].y), fminf(v[k+0].z, v[k+0].w)));
        mx0 = fmaxf(mx0, fmaxf(fmaxf(v[k+0].x, v[k+0].y), fmaxf(v[k+0].z, v[k+0].w)));
        mn1 = fminf(mn1, fminf(fminf(v[k+1].x, v[k+1].y), fminf(v[k+1].z, v[k+1].w)));
        mx1 = fmaxf(mx1, fmaxf(fmaxf(v[k+1].x, v[k+1].y), fmaxf(v[k+1].z, v[k+1].w)));
        mn2 = fminf(mn2, fminf(fminf(v[k+2].x, v[k+2].y), fminf(v[k+2].z, v[k+2].w)));
        mx2 = fmaxf(mx2, fmaxf(fmaxf(v[k+2].x, v[k+2].y), fmaxf(v[k+2].z, v[k+2].w)));
        mn3 = fminf(mn3, fminf(fminf(v[k+3].x, v[k+3].y), fminf(v[k+3].z, v[k+3].w)));
        mx3 = fmaxf(mx3, fmaxf(fmaxf(v[k+3].x, v[k+3].y), fmaxf(v[k+3].z, v[k+3].w)));
    }
    float mn = fminf(fminf(mn0, mn1), fminf(mn2, mn3));
    float mx = fmaxf(fmaxf(mx0, mx1), fmaxf(mx2, mx3));

    // ---- warp-only reduce: no smem, no barriers anywhere ----
#pragma unroll
    for (int off = 16; off > 0; off >>= 1) {
        mn = fminf(mn, __shfl_xor_sync(0xFFFFFFFFu, mn, off));
        mx = fmaxf(mx, __shfl_xor_sync(0xFFFFFFFFu, mx, off));
    }

    float scale = (mx - mn) * (1.0f / 255.0f);
    scale = fminf(fmaxf(scale, 1e-5f), 1e4f);
    float zp = -mn / scale;
    zp = fminf(fmaxf(zp, -1e4f), 1e4f);
    const float inv = 1.0f / scale;

    // ---- fake quant-dequant in place, streaming stores ----
#pragma unroll
    for (int k = 0; k < NV4; ++k) {
        float4 r;
        float q;
        q = rintf(v[k].x * inv) + zp; q = fminf(fmaxf(q, 0.0f), 255.0f); r.x = (q - zp) * scale;
        q = rintf(v[k].y * inv) + zp; q = fminf(fmaxf(q, 0.0f), 255.0f); r.y = (q - zp) * scale;
        q = rintf(v[k].z * inv) + zp; q = fminf(fmaxf(q, 0.0f), 255.0f); r.z = (q - zp) * scale;
        q = rintf(v[k].w * inv) + zp; q = fminf(fmaxf(q, 0.0f), 255.0f); r.w = (q - zp) * scale;
        __stcs(&outr[lid + k * 32], r);
    }
}

extern "C" void kernel_launch(void* const* d_in, const int* in_sizes, int n_in,
                              void* d_out, int out_size)
{
    const float* x = (const float*)d_in[0];
    float* out = (float*)d_out;
    const int n_rows = in_sizes[0] / ROW_LEN;        // 16384
    const int n_blocks = n_rows / WARPS_CTA;         // 4096
    quant_warprow_reg<<<n_blocks, THREADS>>>(x, out);
}